// round 4
// baseline (speedup 1.0000x reference)
#include <cuda_runtime.h>
#include <cuda_bf16.h>
#include <cuda_fp16.h>

// S4D forward, exact diagonal-SSM recurrence:
//   a[d,n]  = exp(dt_d * A_n),  A_n = -0.5*(n+1)
//   cb[d,n] = C[d,n]*B[d,n]*expm1(dt_d*A_n)/A_n
//   h_n[l]  = a_n*h_n[l-1] + x[l],   y[l] = sum_n cb_n*h_n[l] + D_d*x[l]
//
// R4: lane=channel (32-wide coalesced I/O), warp=8-state slice, FFMA2 math.
// Cross-warp partials exchanged as fp16 (4x fewer smem bytes: one LDS.128
// reads a whole 8-partial row), RST=32 (half the barriers), double-buffered
// single-barrier rounds.

#define BATCH   8
#define LEN     2048
#define DMODEL  1024
#define NSTATE  64

#define WARPS   8
#define SPT     8      // states per thread
#define PAIRS   4      // packed f32x2 pairs per thread
#define CHT     32     // channel tile = lanes
#define RST     32     // timesteps per reduction round

typedef unsigned long long u64;

__device__ __forceinline__ u64 pack2(float lo, float hi) {
    u64 r; asm("mov.b64 %0, {%1,%2};" : "=l"(r) : "f"(lo), "f"(hi)); return r;
}
__device__ __forceinline__ void unpack2(u64 v, float& lo, float& hi) {
    asm("mov.b64 {%0,%1}, %2;" : "=f"(lo), "=f"(hi) : "l"(v));
}
__device__ __forceinline__ u64 fma2(u64 a, u64 b, u64 c) {
    u64 d; asm("fma.rn.f32x2 %0, %1, %2, %3;" : "=l"(d) : "l"(a), "l"(b), "l"(c)); return d;
}
__device__ __forceinline__ u64 mul2(u64 a, u64 b) {
    u64 d; asm("mul.rn.f32x2 %0, %1, %2;" : "=l"(d) : "l"(a), "l"(b)); return d;
}

__global__ __launch_bounds__(WARPS * 32)
void s4d_recurrence_kernel(const float* __restrict__ x,
                           const float* __restrict__ log_dt,
                           const float* __restrict__ Bm,
                           const float* __restrict__ Cm,
                           const float* __restrict__ Dv,
                           float* __restrict__ y)
{
    // fp16 partials: P[buf][r][channel][warp] ; row [channel][0..7] = 16B
    __shared__ __half P[2][RST][CHT][WARPS];   // 32 KB

    const int lane = threadIdx.x & 31;
    const int w    = threadIdx.x >> 5;
    const int d    = blockIdx.x * CHT + lane;
    const int b    = blockIdx.y;

    // ---- per-thread discretized parameters (8 states, packed pairs) ----
    u64 a2[PAIRS], cb2[PAIRS], s2[PAIRS];
    {
        const float dt = expf(log_dt[d]);
        #pragma unroll
        for (int i = 0; i < PAIRS; i++) {
            float av[2], cbv[2];
            #pragma unroll
            for (int h = 0; h < 2; h++) {
                const int   n   = w * SPT + 2 * i + h;
                const float An  = -0.5f * (float)(n + 1);
                const float dtA = dt * An;
                av[h]  = expf(dtA);
                cbv[h] = Cm[d * NSTATE + n] * Bm[d * NSTATE + n] * (expm1f(dtA) / An);
            }
            a2[i]  = pack2(av[0], av[1]);
            cb2[i] = pack2(cbv[0], cbv[1]);
            s2[i]  = 0ull;
        }
    }
    const float Dd = Dv[d];

    const float* xb = x + (size_t)b * LEN * DMODEL + d;
    float*       yb = y + (size_t)b * LEN * DMODEL + d;

    #pragma unroll 1
    for (int l0 = 0; l0 < LEN; l0 += 2 * RST) {
        #pragma unroll
        for (int buf = 0; buf < 2; buf++) {
            const int base = l0 + buf * RST;

            // ---- compute: 32 steps of FFMA2 recurrence + contraction ----
            #pragma unroll
            for (int r = 0; r < RST; r++) {
                const float xv = xb[(size_t)(base + r) * DMODEL];
                const u64   xx = pack2(xv, xv);
                s2[0] = fma2(a2[0], s2[0], xx);
                s2[1] = fma2(a2[1], s2[1], xx);
                s2[2] = fma2(a2[2], s2[2], xx);
                s2[3] = fma2(a2[3], s2[3], xx);
                u64 e0 = fma2(cb2[1], s2[1], mul2(cb2[0], s2[0]));
                u64 e1 = fma2(cb2[3], s2[3], mul2(cb2[2], s2[2]));
                float l0f, h0f, l1f, h1f;
                unpack2(e0, l0f, h0f);
                unpack2(e1, l1f, h1f);
                P[buf][r][lane][w] = __float2half((l0f + h0f) + (l1f + h1f));
            }
            __syncthreads();

            // ---- cross-warp reduce: warp w -> rows r = w + 8k; lane=channel.
            //      One LDS.128 grabs all 8 partials of a (row, channel). ----
            #pragma unroll
            for (int k = 0; k < 4; k++) {
                const int r = w + k * WARPS;
                const uint4 rv = *(const uint4*)&P[buf][r][lane][0];
                const float2 f0 = __half22float2(*(const __half2*)&rv.x);
                const float2 f1 = __half22float2(*(const __half2*)&rv.y);
                const float2 f2 = __half22float2(*(const __half2*)&rv.z);
                const float2 f3 = __half22float2(*(const __half2*)&rv.w);
                const float sum = ((f0.x + f0.y) + (f1.x + f1.y))
                                + ((f2.x + f2.y) + (f3.x + f3.y));
                const float xv = xb[(size_t)(base + r) * DMODEL];   // L1 hit
                yb[(size_t)(base + r) * DMODEL] = fmaf(Dd, xv, sum);
            }
            // single barrier per round: buffer `buf` is next overwritten only
            // after the NEXT __syncthreads, so these reads are race-free.
        }
    }
}

extern "C" void kernel_launch(void* const* d_in, const int* in_sizes, int n_in,
                              void* d_out, int out_size)
{
    const float* x      = (const float*)d_in[0];  // [8, 2048, 1024]
    const float* log_dt = (const float*)d_in[1];  // [1024]
    const float* Bm     = (const float*)d_in[2];  // [1024, 64]
    const float* Cm     = (const float*)d_in[3];  // [1024, 64]
    const float* Dv     = (const float*)d_in[4];  // [1024]
    float*       y      = (float*)d_out;          // [8, 2048, 1024]

    dim3 grid(DMODEL / CHT, BATCH);   // (32, 8) = 256 blocks
    dim3 block(WARPS * 32);           // 256 threads
    s4d_recurrence_kernel<<<grid, block>>>(x, log_dt, Bm, Cm, Dv, y);
}

// round 5
// speedup vs baseline: 1.7045x; 1.7045x over previous
#include <cuda_runtime.h>
#include <cuda_bf16.h>

// S4D forward, exact diagonal-SSM recurrence, chunked over L for parallelism:
//   a[d,n]  = exp(dt_d * A_n),  A_n = -0.5*(n+1)
//   cb[d,n] = C[d,n]*B[d,n]*expm1(dt_d*A_n)/A_n
//   h_n[l]  = a_n*h_n[l-1] + x[l],   y[l] = sum_n cb_n*h_n[l] + D_d*x[l]
//
// R5: L split into 4 chunks of 512.
//   K1: chunks 0..2 compute chunk-final states (recurrence only, no smem).
//   K3: all 4 chunks run the full recurrence+contraction with analytic
//       carry-in  h0[c] = sum_{c'<c} exp(dtA*T*(c-1-c')) * S[c'].
// Inner structure = proven R2 body: lane=channel (coalesced), warp=8-state
// slice, packed fma.rn.f32x2, u64 smem partials, single-barrier double-buffer.

#define BATCH   8
#define LEN     2048
#define DMODEL  1024
#define NSTATE  64

#define NCHUNK  4
#define TCH     512    // chunk length

#define WARPS   8
#define SPT     8      // states per thread
#define PAIRS   4
#define CHT     32     // channel tile = lanes
#define RST     16     // timesteps per reduction round

typedef unsigned long long u64;

// chunk-final states: [chunk 0..2][b][d][n]
__device__ float S_scratch[3 * BATCH * DMODEL * NSTATE];

__device__ __forceinline__ u64 pack2(float lo, float hi) {
    u64 r; asm("mov.b64 %0, {%1,%2};" : "=l"(r) : "f"(lo), "f"(hi)); return r;
}
__device__ __forceinline__ void unpack2(u64 v, float& lo, float& hi) {
    asm("mov.b64 {%0,%1}, %2;" : "=f"(lo), "=f"(hi) : "l"(v));
}
__device__ __forceinline__ u64 fma2(u64 a, u64 b, u64 c) {
    u64 d; asm("fma.rn.f32x2 %0, %1, %2, %3;" : "=l"(d) : "l"(a), "l"(b), "l"(c)); return d;
}
__device__ __forceinline__ u64 mul2(u64 a, u64 b) {
    u64 d; asm("mul.rn.f32x2 %0, %1, %2;" : "=l"(d) : "l"(a), "l"(b)); return d;
}
__device__ __forceinline__ u64 add2(u64 a, u64 b) {
    u64 d; asm("add.rn.f32x2 %0, %1, %2;" : "=l"(d) : "l"(a), "l"(b)); return d;
}

// ---------------- K1: chunk-final states for chunks 0..2 ----------------
__global__ __launch_bounds__(WARPS * 32, 6)
void s4d_k1_states(const float* __restrict__ x,
                   const float* __restrict__ log_dt)
{
    const int lane = threadIdx.x & 31;
    const int w    = threadIdx.x >> 5;
    const int d    = blockIdx.x * CHT + lane;
    const int b    = blockIdx.y;
    const int c    = blockIdx.z;          // 0..2

    u64 a2[PAIRS], s2[PAIRS];
    {
        const float dt = expf(log_dt[d]);
        #pragma unroll
        for (int i = 0; i < PAIRS; i++) {
            float av[2];
            #pragma unroll
            for (int h = 0; h < 2; h++) {
                const int n = w * SPT + 2 * i + h;
                av[h] = expf(dt * (-0.5f * (float)(n + 1)));
            }
            a2[i] = pack2(av[0], av[1]);
            s2[i] = 0ull;
        }
    }

    const float* xb = x + ((size_t)b * LEN + (size_t)c * TCH) * DMODEL + d;

    #pragma unroll 1
    for (int l0 = 0; l0 < TCH; l0 += RST) {
        #pragma unroll
        for (int r = 0; r < RST; r++) {
            const float xv = xb[(size_t)(l0 + r) * DMODEL];
            const u64   xx = pack2(xv, xv);
            s2[0] = fma2(a2[0], s2[0], xx);
            s2[1] = fma2(a2[1], s2[1], xx);
            s2[2] = fma2(a2[2], s2[2], xx);
            s2[3] = fma2(a2[3], s2[3], xx);
        }
    }

    u64* Sp = (u64*)(S_scratch + ((((size_t)c * BATCH + b) * DMODEL + d) * NSTATE + w * SPT));
    #pragma unroll
    for (int i = 0; i < PAIRS; i++) Sp[i] = s2[i];
}

// ---------------- K3: full recurrence + contraction per chunk ----------------
__global__ __launch_bounds__(WARPS * 32, 4)
void s4d_k3_main(const float* __restrict__ x,
                 const float* __restrict__ log_dt,
                 const float* __restrict__ Bm,
                 const float* __restrict__ Cm,
                 const float* __restrict__ Dv,
                 float* __restrict__ y)
{
    __shared__ u64 P[2][WARPS][RST][CHT];   // 32 KB

    const int lane = threadIdx.x & 31;
    const int w    = threadIdx.x >> 5;
    const int d    = blockIdx.x * CHT + lane;
    const int b    = blockIdx.y;
    const int c    = blockIdx.z;          // 0..3

    u64 a2[PAIRS], cb2[PAIRS], s2[PAIRS];
    {
        const float dt = expf(log_dt[d]);
        #pragma unroll
        for (int i = 0; i < PAIRS; i++) {
            float av[2], cbv[2], dtAv[2];
            #pragma unroll
            for (int h = 0; h < 2; h++) {
                const int   n   = w * SPT + 2 * i + h;
                const float An  = -0.5f * (float)(n + 1);
                const float dtA = dt * An;
                dtAv[h] = dtA;
                av[h]   = expf(dtA);
                cbv[h]  = Cm[d * NSTATE + n] * Bm[d * NSTATE + n] * (expm1f(dtA) / An);
            }
            a2[i]  = pack2(av[0], av[1]);
            cb2[i] = pack2(cbv[0], cbv[1]);

            // carry-in: h0 = sum_{c'<c} exp(dtA * T * (c-1-c')) * S[c']
            float h0lo = 0.0f, h0hi = 0.0f;
            for (int cp = 0; cp < c; cp++) {
                const u64 sv = *(const u64*)(S_scratch +
                    ((((size_t)cp * BATCH + b) * DMODEL + d) * NSTATE + w * SPT + 2 * i));
                float slo, shi;
                unpack2(sv, slo, shi);
                const float k = (float)(TCH * (c - 1 - cp));
                h0lo += expf(dtAv[0] * k) * slo;
                h0hi += expf(dtAv[1] * k) * shi;
            }
            s2[i] = pack2(h0lo, h0hi);
        }
    }
    const float Dd = Dv[d];

    const float* xb = x + ((size_t)b * LEN + (size_t)c * TCH) * DMODEL + d;
    float*       yb = y + ((size_t)b * LEN + (size_t)c * TCH) * DMODEL + d;

    #pragma unroll 1
    for (int l0 = 0; l0 < TCH; l0 += 2 * RST) {
        #pragma unroll
        for (int buf = 0; buf < 2; buf++) {
            const int base = l0 + buf * RST;

            // ---- compute: 16 steps, packed FFMA2, partials -> smem ----
            #pragma unroll
            for (int r = 0; r < RST; r++) {
                const float xv = xb[(size_t)(base + r) * DMODEL];
                const u64   xx = pack2(xv, xv);
                s2[0] = fma2(a2[0], s2[0], xx);
                s2[1] = fma2(a2[1], s2[1], xx);
                s2[2] = fma2(a2[2], s2[2], xx);
                s2[3] = fma2(a2[3], s2[3], xx);
                u64 acc = mul2(cb2[0], s2[0]);
                acc = fma2(cb2[1], s2[1], acc);
                acc = fma2(cb2[2], s2[2], acc);
                acc = fma2(cb2[3], s2[3], acc);
                P[buf][w][r][lane] = acc;
            }
            __syncthreads();

            // ---- cross-warp reduce: warp w -> rows r=w, w+8 ----
            #pragma unroll
            for (int k = 0; k < 2; k++) {
                const int r = w + k * WARPS;
                u64 sum = P[buf][0][r][lane];
                #pragma unroll
                for (int ww = 1; ww < WARPS; ww++)
                    sum = add2(sum, P[buf][ww][r][lane]);
                float lo, hi;
                unpack2(sum, lo, hi);
                const float xv = xb[(size_t)(base + r) * DMODEL];  // L1/L2 hit
                yb[(size_t)(base + r) * DMODEL] = fmaf(Dd, xv, lo + hi);
            }
            // single barrier per round: this buffer is next overwritten only
            // after the NEXT __syncthreads, so these reads are race-free.
        }
    }
}

extern "C" void kernel_launch(void* const* d_in, const int* in_sizes, int n_in,
                              void* d_out, int out_size)
{
    const float* x      = (const float*)d_in[0];  // [8, 2048, 1024]
    const float* log_dt = (const float*)d_in[1];  // [1024]
    const float* Bm     = (const float*)d_in[2];  // [1024, 64]
    const float* Cm     = (const float*)d_in[3];  // [1024, 64]
    const float* Dv     = (const float*)d_in[4];  // [1024]
    float*       y      = (float*)d_out;          // [8, 2048, 1024]

    dim3 block(WARPS * 32);

    dim3 g1(DMODEL / CHT, BATCH, NCHUNK - 1);     // (32, 8, 3) = 768 CTAs
    s4d_k1_states<<<g1, block>>>(x, log_dt);

    dim3 g3(DMODEL / CHT, BATCH, NCHUNK);         // (32, 8, 4) = 1024 CTAs
    s4d_k3_main<<<g3, block>>>(x, log_dt, Bm, Cm, Dv, y);
}